// round 10
// baseline (speedup 1.0000x reference)
#include <cuda_runtime.h>
#include <cstdint>

// CRF negative log-likelihood, B=256, T=2048, D=64.
// Warp-synchronous recursion: ONE warp per chain, no cross-warp barriers.
//   Lane l owns states j0=l and j1=l+32. Full 64-wide i-sum per state via
//   64 packed fma.rn.f32x2 per lane per step; expT coefficient pairs live in
//   128 registers. u exchanged via shared double-buffer + __syncwarp only.
//   RN=8 renormalization: S = warp-butterfly of the k==7 output (latency
//   hidden over next 8 steps), scale folded into precomputed ex[0].
// CTA = 128 threads: warps 0-1 = recursion for chains 2b, 2b+1;
//   warps 2-3 = scoring (L, emission s1, transition s2) for the same chains.
// Grid = 128 CTAs.

#define TT 2048
#define DD 64

typedef unsigned long long ull;

#define FMA2(d,a,b,c)  asm("fma.rn.f32x2 %0, %1, %2, %3;" : "=l"(d) : "l"(a), "l"(b), "l"(c))
#define ADD2(d,a,b)    asm("add.rn.f32x2 %0, %1, %2;"     : "=l"(d) : "l"(a), "l"(b))
#define PACK2(d,lo,hi) asm("mov.b64 %0, {%1, %2};"        : "=l"(d) : "f"(lo), "f"(hi))
#define UNPACK2(lo,hi,v) asm("mov.b64 {%0, %1}, %2;"      : "=f"(lo), "=f"(hi) : "l"(v))

__device__ __forceinline__ float warp_sum(float v) {
    #pragma unroll
    for (int s = 16; s >= 1; s >>= 1) v += __shfl_xor_sync(0xffffffffu, v, s);
    return v;
}

__global__ __launch_bounds__(128, 1)
void crf_warp(const float* __restrict__ p,
              const int*   __restrict__ y,
              const int*   __restrict__ mask,
              const float* __restrict__ trans,
              float*       __restrict__ out)
{
    const int bid = blockIdx.x;         // 0..127, chains 2*bid, 2*bid+1
    const int w   = threadIdx.x >> 5;
    const int l   = threadIdx.x & 31;

    __shared__ __align__(16) float ubuf[2][2][DD];   // [chain][buf][state]
    __shared__ short lab[2][TT];
    __shared__ float sred[2];
    __shared__ float lzred[2];

    if (w < 2) {
        // ================= recursion warp: chain c =================
        const int c = bid * 2 + w;

        // ---- length L ----
        const int4* mb4 = reinterpret_cast<const int4*>(mask + (size_t)c * TT);
        int ms = 0;
        #pragma unroll
        for (int k = 0; k < 16; k++) {
            int4 v = mb4[l + 32 * k];
            ms += v.x + v.y + v.z + v.w;
        }
        #pragma unroll
        for (int s = 16; s >= 1; s >>= 1) ms += __shfl_xor_sync(0xffffffffu, ms, s);
        const int L = TT - ms;

        // ---- expT coefficient pairs in registers ----
        // c0[q] = (expT[2q][l],    expT[2q+1][l])
        // c1[q] = (expT[2q][l+32], expT[2q+1][l+32])
        ull c0[32], c1[32];
        #pragma unroll
        for (int q = 0; q < 32; q++) {
            float a = __expf(trans[(2 * q)     * DD + l]);
            float b = __expf(trans[(2 * q + 1) * DD + l]);
            PACK2(c0[q], a, b);
            float e = __expf(trans[(2 * q)     * DD + l + 32]);
            float f = __expf(trans[(2 * q + 1) * DD + l + 32]);
            PACK2(c1[q], e, f);
        }

        const float* pb = p + (size_t)c * TT * DD;

        // ---- t = 0 prologue ----
        float v0 = __expf(pb[l]);
        float v1 = __expf(pb[l + 32]);
        ubuf[w][0][l]      = v0;
        ubuf[w][0][l + 32] = v1;
        float Spend = warp_sum(v0 + v1);   // sum of u0, folded at block 1 start
        float logz  = 0.f;

        // preload p for t = 1..8
        float pf0[8], pf1[8];
        #pragma unroll
        for (int k = 0; k < 8; k++) {
            int t = 1 + k;
            pf0[k] = (t < L) ? pb[(size_t)t * DD + l]      : 0.f;
            pf1[k] = (t < L) ? pb[(size_t)t * DD + l + 32] : 0.f;
        }
        __syncwarp();

        int base = 1;

        // ---- full blocks of 8 steps ----
        while (base + 7 <= L - 1) {
            const float rinv = __fdividef(1.f, Spend);
            logz += __logf(Spend);
            float ex0[8], ex1[8];
            #pragma unroll
            for (int k = 0; k < 8; k++) { ex0[k] = __expf(pf0[k]); ex1[k] = __expf(pf1[k]); }
            ex0[0] *= rinv; ex1[0] *= rinv;
            // burst-prefetch next block
            #pragma unroll
            for (int k = 0; k < 8; k++) {
                int t2 = base + 8 + k;
                pf0[k] = (t2 < L) ? pb[(size_t)t2 * DD + l]      : 0.f;
                pf1[k] = (t2 < L) ? pb[(size_t)t2 * DD + l + 32] : 0.f;
            }

            #pragma unroll
            for (int k = 0; k < 8; k++) {
                const int t  = base + k;
                const int wb = t & 1, rb = wb ^ 1;
                const ulonglong2* ub =
                    reinterpret_cast<const ulonglong2*>(ubuf[w][rb]);
                ull a0 = 0, a1 = 0, a2 = 0, a3 = 0;   // state j0: 4 chains
                ull b0 = 0, b1 = 0, b2 = 0, b3 = 0;   // state j1: 4 chains
                #pragma unroll
                for (int q = 0; q < 8; q++) {
                    ulonglong2 uA = ub[2 * q];        // u[8q..8q+3] as 2 pairs
                    ulonglong2 uB = ub[2 * q + 1];    // u[8q+4..8q+7]
                    FMA2(a0, uA.x, c0[4 * q + 0], a0);
                    FMA2(a1, uA.y, c0[4 * q + 1], a1);
                    FMA2(a2, uB.x, c0[4 * q + 2], a2);
                    FMA2(a3, uB.y, c0[4 * q + 3], a3);
                    FMA2(b0, uA.x, c1[4 * q + 0], b0);
                    FMA2(b1, uA.y, c1[4 * q + 1], b1);
                    FMA2(b2, uB.x, c1[4 * q + 2], b2);
                    FMA2(b3, uB.y, c1[4 * q + 3], b3);
                }
                ADD2(a0, a0, a1); ADD2(a2, a2, a3); ADD2(a0, a0, a2);
                ADD2(b0, b0, b1); ADD2(b2, b2, b3); ADD2(b0, b0, b2);
                float lo, hi;
                UNPACK2(lo, hi, a0); float acc0 = lo + hi;
                UNPACK2(lo, hi, b0); float acc1 = lo + hi;
                v0 = ex0[k] * acc0;
                v1 = ex1[k] * acc1;
                ubuf[w][wb][l]      = v0;
                ubuf[w][wb][l + 32] = v1;
                if (k == 7) Spend = warp_sum(v0 + v1);  // latency hidden: used 8 steps later
                __syncwarp();
            }
            base += 8;
        }

        // ---- remainder: t = base .. L-1 (pf already holds these) ----
        if (base <= L - 1) {
            const float rinv = __fdividef(1.f, Spend);
            logz += __logf(Spend);
            for (int t = base; t <= L - 1; t++) {
                const int k = t - base;
                float e0 = __expf(pf0[k]);
                float e1 = __expf(pf1[k]);
                if (k == 0) { e0 *= rinv; e1 *= rinv; }
                const int wb = t & 1, rb = wb ^ 1;
                const ulonglong2* ub =
                    reinterpret_cast<const ulonglong2*>(ubuf[w][rb]);
                ull a0 = 0, a1 = 0, a2 = 0, a3 = 0;
                ull b0 = 0, b1 = 0, b2 = 0, b3 = 0;
                #pragma unroll
                for (int q = 0; q < 8; q++) {
                    ulonglong2 uA = ub[2 * q];
                    ulonglong2 uB = ub[2 * q + 1];
                    FMA2(a0, uA.x, c0[4 * q + 0], a0);
                    FMA2(a1, uA.y, c0[4 * q + 1], a1);
                    FMA2(a2, uB.x, c0[4 * q + 2], a2);
                    FMA2(a3, uB.y, c0[4 * q + 3], a3);
                    FMA2(b0, uA.x, c1[4 * q + 0], b0);
                    FMA2(b1, uA.y, c1[4 * q + 1], b1);
                    FMA2(b2, uB.x, c1[4 * q + 2], b2);
                    FMA2(b3, uB.y, c1[4 * q + 3], b3);
                }
                ADD2(a0, a0, a1); ADD2(a2, a2, a3); ADD2(a0, a0, a2);
                ADD2(b0, b0, b1); ADD2(b2, b2, b3); ADD2(b0, b0, b2);
                float lo, hi;
                UNPACK2(lo, hi, a0); float acc0 = lo + hi;
                UNPACK2(lo, hi, b0); float acc1 = lo + hi;
                v0 = e0 * acc0;
                v1 = e1 * acc1;
                ubuf[w][wb][l]      = v0;
                ubuf[w][wb][l + 32] = v1;
                __syncwarp();
            }
        }
        // note: if no remainder, logz still excludes the last block's Spend,
        // and final u was never rescaled — epilogue sums smem directly either way.
        if (l == 0) lzred[w] = logz;
    } else {
        // ================= scoring warp: chain c =================
        const int c  = bid * 2 + (w - 2);
        const int ch = w - 2;

        // length L (own copy)
        const int4* mb4 = reinterpret_cast<const int4*>(mask + (size_t)c * TT);
        int ms = 0;
        #pragma unroll
        for (int k = 0; k < 16; k++) {
            int4 v = mb4[l + 32 * k];
            ms += v.x + v.y + v.z + v.w;
        }
        #pragma unroll
        for (int s = 16; s >= 1; s >>= 1) ms += __shfl_xor_sync(0xffffffffu, ms, s);
        const int L = TT - ms;

        // labels from one-hot: lane l handles rows l, l+32, ...
        const int4* yb4 = reinterpret_cast<const int4*>(y + (size_t)c * TT * DD);
        for (int t = l; t < TT; t += 32) {
            const int4* row = yb4 + (size_t)t * 16;
            int lv = 0;
            #pragma unroll
            for (int k = 0; k < 16; k++) {
                int4 v = row[k];
                lv += v.x * (4 * k) + v.y * (4 * k + 1) + v.z * (4 * k + 2) + v.w * (4 * k + 3);
            }
            lab[ch][t] = (short)lv;
        }
        __syncwarp();

        const float* pb = p + (size_t)c * TT * DD;
        float s = 0.f;
        for (int t = l; t < L; t += 32) {
            int lt = lab[ch][t];
            s += pb[(size_t)t * DD + lt];
            if (t < L - 1) s += trans[lt * DD + lab[ch][t + 1]];
        }
        s = warp_sum(s);
        if (l == 0) sred[ch] = s;
    }

    __syncthreads();

    // ================= epilogue (recursion warps) =================
    if (w < 2) {
        const int c = bid * 2 + w;
        // recompute L cheaply? kept in registers above — recompute fb from L:
        // L is live in this branch (same scope), reuse it:
        // (compiler keeps it; recompute not needed)
        ;
    }
    if (w < 2) {
        // L still in scope from the recursion branch
        // final sum over u[(L-1)&1]
        // NOTE: we re-derive L here from mask to keep scoping simple & cheap.
        const int c = bid * 2 + w;
        const int4* mb4 = reinterpret_cast<const int4*>(mask + (size_t)c * TT);
        int ms = 0;
        #pragma unroll
        for (int k = 0; k < 16; k++) {
            int4 v = mb4[l + 32 * k];
            ms += v.x + v.y + v.z + v.w;
        }
        #pragma unroll
        for (int s = 16; s >= 1; s >>= 1) ms += __shfl_xor_sync(0xffffffffu, ms, s);
        const int L  = TT - ms;
        const int fb = (L - 1) & 1;
        float fv = ubuf[w][fb][l] + ubuf[w][fb][l + 32];
        float Sf = warp_sum(fv);
        if (l == 0) out[c] = lzred[w] + __logf(Sf) - sred[w];
    }
}

extern "C" void kernel_launch(void* const* d_in, const int* in_sizes, int n_in,
                              void* d_out, int out_size) {
    const float* p     = (const float*)d_in[0];
    const int*   y     = (const int*)d_in[1];
    const int*   mask  = (const int*)d_in[2];
    const float* trans = (const float*)d_in[3];
    float* out = (float*)d_out;
    (void)in_sizes; (void)n_in; (void)out_size;
    crf_warp<<<128, 128>>>(p, y, mask, trans, out);
}

// round 13
// speedup vs baseline: 2.4753x; 2.4753x over previous
#include <cuda_runtime.h>
#include <cstdint>
#include <math.h>

// CRF NLL, B=256, T=2048, D=64 — bidirectional forward/backward recursion.
// One CTA (256 thr) per batch:
//   Phase A (all 8 warps): length L, labels, emission+transition score s12.
//   Phase B: warps 0-3 forward chain u_t (bar.sync 1,128),
//            warps 4-7 backward chain c_t (bar.sync 3,128), m=(L-1)/2.
//     Both use the measured-best R9 step structure: 16 FFMA2/thread,
//     lane-half i-split + shfl16, RN=8 renorm folded into precomputed exps,
//     8-deep register prefetch of p.
//   Epilogue: Z = u_m^T (E c_{m+1}) combined in double; out = lzF+lzB+log(S)-s12.

#define TT 2048
#define DD 64

typedef unsigned long long ull;

#define FMA2(d,a,b,c)  asm("fma.rn.f32x2 %0, %1, %2, %3;" : "=l"(d) : "l"(a), "l"(b), "l"(c))
#define ADD2(d,a,b)    asm("add.rn.f32x2 %0, %1, %2;"     : "=l"(d) : "l"(a), "l"(b))
#define PACK2(d,lo,hi) asm("mov.b64 %0, {%1, %2};"        : "=l"(d) : "f"(lo), "f"(hi))
#define UNPACK2(lo,hi,v) asm("mov.b64 {%0, %1}, %2;"      : "=f"(lo), "=f"(hi) : "l"(v))
#define BARF() asm volatile("bar.sync 1, 128;" ::: "memory")
#define BARB() asm volatile("bar.sync 3, 128;" ::: "memory")

__global__ __launch_bounds__(256, 2)
void crf_bidir(const float* __restrict__ p,
               const int*   __restrict__ y,
               const int*   __restrict__ mask,
               const float* __restrict__ trans,
               float*       __restrict__ out)
{
    const int b   = blockIdx.x;
    const int tid = threadIdx.x;
    const int w   = tid >> 5;
    const int l   = tid & 31;
    const int h   = l >> 4;                     // i-half
    const int j   = ((w & 3) << 4) | (l & 15);  // state

    __shared__ short lab[TT];
    __shared__ __align__(16) float ubufF[2][DD];
    __shared__ __align__(16) float ubufB[2][DD];
    __shared__ float sred[8];
    __shared__ int   ired[8];
    __shared__ float lzF, lzB, s12sh;

    const float* pb = p + (size_t)b * TT * DD;

    // ================= Phase A: L, labels, s12 (all 8 warps) =================
    {
        const int4* mb4 = reinterpret_cast<const int4*>(mask + (size_t)b * TT);
        int ms = 0;
        #pragma unroll
        for (int k = 0; k < 2; k++) {
            int4 v = mb4[tid + 256 * k];
            ms += v.x + v.y + v.z + v.w;
        }
        #pragma unroll
        for (int s = 16; s >= 1; s >>= 1) ms += __shfl_xor_sync(0xffffffffu, ms, s);
        if (l == 0) ired[w] = ms;

        const int4* yb4 = reinterpret_cast<const int4*>(y + (size_t)b * TT * DD);
        for (int t = tid; t < TT; t += 256) {
            const int4* row = yb4 + (size_t)t * 16;
            int lv = 0;
            #pragma unroll
            for (int k = 0; k < 16; k++) {
                int4 v = row[k];
                lv += v.x * (4 * k) + v.y * (4 * k + 1) + v.z * (4 * k + 2) + v.w * (4 * k + 3);
            }
            lab[t] = (short)lv;
        }
        __syncthreads();
    }
    const int L = TT - (ired[0] + ired[1] + ired[2] + ired[3] +
                        ired[4] + ired[5] + ired[6] + ired[7]);
    {
        float s = 0.f;
        for (int t = tid; t < L; t += 256) {
            int lt = lab[t];
            s += pb[(size_t)t * DD + lt];
            if (t < L - 1) s += trans[lt * DD + lab[t + 1]];
        }
        #pragma unroll
        for (int ss = 16; ss >= 1; ss >>= 1) s += __shfl_xor_sync(0xffffffffu, s, ss);
        if (l == 0) sred[w] = s;
        __syncthreads();
        if (tid == 0)
            s12sh = sred[0] + sred[1] + sred[2] + sred[3] +
                    sred[4] + sred[5] + sred[6] + sred[7];
    }

    const int m = (L - 1) >> 1;        // forward endpoint; fwd does m steps
    const int NBtot = L - 1 - m;       // backward matvec count (last one ex=1)
    const int NB = NBtot - 1;          // backward emission steps

    // ================= Phase B =================
    if (tid < 128) {
        // ---------- forward chain: u_t, t = 1..m ----------
        ull col2[16];   // pairs over i: expT[i][j]
        #pragma unroll
        for (int k2 = 0; k2 < 16; k2++) {
            float c0 = __expf(trans[(h * 32 + 2 * k2)     * DD + j]);
            float c1 = __expf(trans[(h * 32 + 2 * k2 + 1) * DD + j]);
            PACK2(col2[k2], c0, c1);
        }
        if (h == 0) ubufF[0][j] = __expf(pb[j]);

        float pf[8], exs[8];
        #pragma unroll
        for (int k = 0; k < 8; k++) pf[k] = 0.f;
        if (h == 0) {
            #pragma unroll
            for (int k = 0; k < 8; k++)
                if (1 + k <= m) pf[k] = pb[(size_t)(1 + k) * DD + j];
        }
        float Spend = 1.f, logz = 0.f;
        int base = 1;
        BARF();

        while (base + 7 <= m) {
            #pragma unroll
            for (int k = 0; k < 8; k++) exs[k] = __expf(pf[k]);
            exs[0] *= __fdividef(1.f, Spend);
            logz += __logf(Spend);
            if (h == 0) {
                #pragma unroll
                for (int k = 0; k < 8; k++) {
                    int t2 = base + 8 + k;
                    pf[k] = (t2 <= m) ? pb[(size_t)t2 * DD + j] : 0.f;
                }
            }
            #pragma unroll
            for (int k = 0; k < 8; k++) {
                const int t  = base + k;
                const int wb = t & 1, rb = wb ^ 1;
                const ulonglong2* ub =
                    reinterpret_cast<const ulonglong2*>(&ubufF[rb][h * 32]);
                ull a0 = 0, a1 = 0, a2 = 0, a3 = 0, ss0 = 0, ss1 = 0;
                #pragma unroll
                for (int q = 0; q < 4; q++) {
                    ulonglong2 u01 = ub[2 * q];
                    ulonglong2 u23 = ub[2 * q + 1];
                    FMA2(a0, u01.x, col2[4 * q + 0], a0);
                    FMA2(a1, u01.y, col2[4 * q + 1], a1);
                    FMA2(a2, u23.x, col2[4 * q + 2], a2);
                    FMA2(a3, u23.y, col2[4 * q + 3], a3);
                    if (k == 7) {
                        ADD2(ss0, ss0, u01.x); ADD2(ss0, ss0, u23.x);
                        ADD2(ss1, ss1, u01.y); ADD2(ss1, ss1, u23.y);
                    }
                }
                ADD2(a0, a0, a1); ADD2(a2, a2, a3); ADD2(a0, a0, a2);
                float lo, hi; UNPACK2(lo, hi, a0);
                float acc = lo + hi;
                acc += __shfl_xor_sync(0xffffffffu, acc, 16);
                if (h == 0) ubufF[wb][j] = exs[k] * acc;
                if (k == 7) {
                    ADD2(ss0, ss0, ss1);
                    float slo, shi; UNPACK2(slo, shi, ss0);
                    float Sh = slo + shi;
                    Sh += __shfl_xor_sync(0xffffffffu, Sh, 16);
                    Spend = Sh;
                }
                BARF();
            }
            base += 8;
        }
        if (base <= m) {
            const float rinvr = __fdividef(1.f, Spend);
            logz += __logf(Spend);
            for (int t = base; t <= m; t++) {
                const int k = t - base;
                float ex = 0.f;
                if (h == 0) {
                    ex = __expf(pf[k]);
                    if (k == 0) ex *= rinvr;
                }
                const int wb = t & 1, rb = wb ^ 1;
                const ulonglong2* ub =
                    reinterpret_cast<const ulonglong2*>(&ubufF[rb][h * 32]);
                ull a0 = 0, a1 = 0, a2 = 0, a3 = 0;
                #pragma unroll
                for (int q = 0; q < 4; q++) {
                    ulonglong2 u01 = ub[2 * q];
                    ulonglong2 u23 = ub[2 * q + 1];
                    FMA2(a0, u01.x, col2[4 * q + 0], a0);
                    FMA2(a1, u01.y, col2[4 * q + 1], a1);
                    FMA2(a2, u23.x, col2[4 * q + 2], a2);
                    FMA2(a3, u23.y, col2[4 * q + 3], a3);
                }
                ADD2(a0, a0, a1); ADD2(a2, a2, a3); ADD2(a0, a0, a2);
                float lo, hi; UNPACK2(lo, hi, a0);
                float acc = lo + hi;
                acc += __shfl_xor_sync(0xffffffffu, acc, 16);
                if (h == 0) ubufF[wb][j] = ex * acc;
                BARF();
            }
        }
        if (tid == 0) lzF = logz;
    } else {
        // ---------- backward chain: c_t = exp(p_t) ⊙ (E c_{t+1}) ----------
        // step n (t = L-1-n): n = 1..NBtot; n == NBtot uses ex = 1 (the E·c matvec).
        ull colB[16];   // pairs over i: expT[j][i] (row-major, contiguous)
        #pragma unroll
        for (int k2 = 0; k2 < 16; k2++) {
            float c0 = __expf(trans[j * DD + h * 32 + 2 * k2]);
            float c1 = __expf(trans[j * DD + h * 32 + 2 * k2 + 1]);
            PACK2(colB[k2], c0, c1);
        }
        if (h == 0) ubufB[0][j] = __expf(pb[(size_t)(L - 1) * DD + j]);

        float pf[8], exs[8];
        #pragma unroll
        for (int k = 0; k < 8; k++) pf[k] = 0.f;
        if (h == 0) {
            #pragma unroll
            for (int k = 0; k < 8; k++) {
                int n = 1 + k;
                if (n <= NB) pf[k] = pb[(size_t)(L - 1 - n) * DD + j];
            }
        }
        float Spend = 1.f, logz = 0.f;
        int base = 1;
        BARB();

        while (base + 7 <= NBtot) {
            #pragma unroll
            for (int k = 0; k < 8; k++)
                exs[k] = (base + k <= NB) ? __expf(pf[k]) : 1.f;
            exs[0] *= __fdividef(1.f, Spend);
            logz += __logf(Spend);
            if (h == 0) {
                #pragma unroll
                for (int k = 0; k < 8; k++) {
                    int n2 = base + 8 + k;
                    pf[k] = (n2 <= NB) ? pb[(size_t)(L - 1 - n2) * DD + j] : 0.f;
                }
            }
            #pragma unroll
            for (int k = 0; k < 8; k++) {
                const int n  = base + k;
                const int wb = n & 1, rb = wb ^ 1;
                const ulonglong2* ub =
                    reinterpret_cast<const ulonglong2*>(&ubufB[rb][h * 32]);
                ull a0 = 0, a1 = 0, a2 = 0, a3 = 0, ss0 = 0, ss1 = 0;
                #pragma unroll
                for (int q = 0; q < 4; q++) {
                    ulonglong2 u01 = ub[2 * q];
                    ulonglong2 u23 = ub[2 * q + 1];
                    FMA2(a0, u01.x, colB[4 * q + 0], a0);
                    FMA2(a1, u01.y, colB[4 * q + 1], a1);
                    FMA2(a2, u23.x, colB[4 * q + 2], a2);
                    FMA2(a3, u23.y, colB[4 * q + 3], a3);
                    if (k == 7) {
                        ADD2(ss0, ss0, u01.x); ADD2(ss0, ss0, u23.x);
                        ADD2(ss1, ss1, u01.y); ADD2(ss1, ss1, u23.y);
                    }
                }
                ADD2(a0, a0, a1); ADD2(a2, a2, a3); ADD2(a0, a0, a2);
                float lo, hi; UNPACK2(lo, hi, a0);
                float acc = lo + hi;
                acc += __shfl_xor_sync(0xffffffffu, acc, 16);
                if (h == 0) ubufB[wb][j] = exs[k] * acc;
                if (k == 7) {
                    ADD2(ss0, ss0, ss1);
                    float slo, shi; UNPACK2(slo, shi, ss0);
                    float Sh = slo + shi;
                    Sh += __shfl_xor_sync(0xffffffffu, Sh, 16);
                    Spend = Sh;
                }
                BARB();
            }
            base += 8;
        }
        if (base <= NBtot) {
            const float rinvr = __fdividef(1.f, Spend);
            logz += __logf(Spend);
            for (int n = base; n <= NBtot; n++) {
                const int k = n - base;
                float ex = 0.f;
                if (h == 0) {
                    ex = (n <= NB) ? __expf(pf[k]) : 1.f;
                    if (k == 0) ex *= rinvr;
                }
                const int wb = n & 1, rb = wb ^ 1;
                const ulonglong2* ub =
                    reinterpret_cast<const ulonglong2*>(&ubufB[rb][h * 32]);
                ull a0 = 0, a1 = 0, a2 = 0, a3 = 0;
                #pragma unroll
                for (int q = 0; q < 4; q++) {
                    ulonglong2 u01 = ub[2 * q];
                    ulonglong2 u23 = ub[2 * q + 1];
                    FMA2(a0, u01.x, colB[4 * q + 0], a0);
                    FMA2(a1, u01.y, colB[4 * q + 1], a1);
                    FMA2(a2, u23.x, colB[4 * q + 2], a2);
                    FMA2(a3, u23.y, colB[4 * q + 3], a3);
                }
                ADD2(a0, a0, a1); ADD2(a2, a2, a3); ADD2(a0, a0, a2);
                float lo, hi; UNPACK2(lo, hi, a0);
                float acc = lo + hi;
                acc += __shfl_xor_sync(0xffffffffu, acc, 16);
                if (h == 0) ubufB[wb][j] = ex * acc;
                BARB();
            }
        }
        if (tid == 128) lzB = logz;
    }
    __syncthreads();

    // ================= epilogue: Z = u_m^T d, combined in double =================
    if (tid < 32) {
        const int fb = m & 1;
        const int db = NBtot & 1;
        double prod = (double)ubufF[fb][l]      * (double)ubufB[db][l]
                    + (double)ubufF[fb][l + 32] * (double)ubufB[db][l + 32];
        #pragma unroll
        for (int s = 16; s >= 1; s >>= 1)
            prod += __shfl_xor_sync(0xffffffffu, prod, s);
        if (l == 0)
            out[b] = lzF + lzB + (float)log(prod) - s12sh;
    }
}

extern "C" void kernel_launch(void* const* d_in, const int* in_sizes, int n_in,
                              void* d_out, int out_size) {
    const float* p     = (const float*)d_in[0];
    const int*   y     = (const int*)d_in[1];
    const int*   mask  = (const int*)d_in[2];
    const float* trans = (const float*)d_in[3];
    float* out = (float*)d_out;
    (void)in_sizes; (void)n_in; (void)out_size;
    crf_bidir<<<256, 256>>>(p, y, mask, trans, out);
}